// round 1
// baseline (speedup 1.0000x reference)
#include <cuda_runtime.h>
#include <math.h>

// Problem constants
#define NS   2048
#define NBAT 2
#define ND   768
#define NH   12
#define NDH  64
static const float SCORE_SCALE = 0.125f;   // 1/sqrt(64) * smoothing(1.0)

// ---------------- scratch (device globals; no allocations allowed) ----------------
__device__ float g_W5[5][768 * 768];                       // permuted weights [k][h*64+d]
__device__ float g_Q [4096 * 768];                         // inp @ WqP   [b*s][h*64+d]
__device__ float g_K [4096 * 768];
__device__ float g_V [4096 * 768];
__device__ float g_Qp[2048 * 768];
__device__ float g_Kp[2048 * 768];
__device__ float g_Pinp[(size_t)2 * 12 * 2048 * 2048];     // softmax(QK) per plane [b*12+h][i][j]
__device__ float g_Ppos[(size_t)12 * 2048 * 2048];         // pos stream  [h][i][j]
__device__ float g_AO[4096 * 768];                         // attn_out pre-Wo [b*s][h*64+d]

// ---------------- weight permutation: Wp[k][h*64+d] = W[k][d*12+h] ----------------
__global__ void permW(const float* __restrict__ W, float* __restrict__ Wp) {
    int idx = blockIdx.x * 256 + threadIdx.x;      // 768*768 = 589824
    if (idx >= 768 * 768) return;
    int k  = idx / 768;
    int oc = idx - k * 768;
    int h = oc >> 6, d = oc & 63;
    Wp[idx] = W[k * 768 + d * 12 + h];
}

// ---------------- generic SGEMM: C[M,N] = A[M,K] @ B[K,N] (row-major) ----------------
// BM=BN=64, BK=16, 256 threads, 4x4 micro-tile. M%64==0, N%64==0, K%16==0.
__global__ void __launch_bounds__(256) sgemm64(const float* __restrict__ A,
                                               const float* __restrict__ B,
                                               float* __restrict__ C,
                                               int M, int N, int K) {
    __shared__ float As[64][17];   // [i][k]
    __shared__ float Bs[16][68];   // [k][n]
    int tid  = threadIdx.x;
    int row0 = blockIdx.x * 64, col0 = blockIdx.y * 64;
    int posI = tid >> 4, posD = tid & 15;
    int i0 = posI * 4, d0 = posD * 4;
    int ar = tid >> 2, ak = (tid & 3) * 4;
    int bk = tid >> 4, bn = (tid & 15) * 4;
    float acc[4][4] = {};
    for (int k0 = 0; k0 < K; k0 += 16) {
        float4 av = *(const float4*)(A + (size_t)(row0 + ar) * K + k0 + ak);
        As[ar][ak] = av.x; As[ar][ak + 1] = av.y; As[ar][ak + 2] = av.z; As[ar][ak + 3] = av.w;
        float4 bv = *(const float4*)(B + (size_t)(k0 + bk) * N + col0 + bn);
        *(float4*)&Bs[bk][bn] = bv;
        __syncthreads();
#pragma unroll
        for (int k = 0; k < 16; k++) {
            float a0 = As[i0][k], a1 = As[i0 + 1][k], a2 = As[i0 + 2][k], a3 = As[i0 + 3][k];
            float4 b4 = *(const float4*)&Bs[k][d0];
            acc[0][0] += a0 * b4.x; acc[0][1] += a0 * b4.y; acc[0][2] += a0 * b4.z; acc[0][3] += a0 * b4.w;
            acc[1][0] += a1 * b4.x; acc[1][1] += a1 * b4.y; acc[1][2] += a1 * b4.z; acc[1][3] += a1 * b4.w;
            acc[2][0] += a2 * b4.x; acc[2][1] += a2 * b4.y; acc[2][2] += a2 * b4.z; acc[2][3] += a2 * b4.w;
            acc[3][0] += a3 * b4.x; acc[3][1] += a3 * b4.y; acc[3][2] += a3 * b4.z; acc[3][3] += a3 * b4.w;
        }
        __syncthreads();
    }
#pragma unroll
    for (int ii = 0; ii < 4; ii++) {
        float4 o = make_float4(acc[ii][0], acc[ii][1], acc[ii][2], acc[ii][3]);
        *(float4*)(C + (size_t)(row0 + i0 + ii) * N + col0 + d0) = o;
    }
}

// ---------------- scores + softmax per (b, h, 16-row i-tile) ----------------
// Writes normalized probs to P at plane (blockIdx.z*12 + h), layout [plane][i][j], coalesced.
// Dynamic smem: sc[16][2048] + Qs[16][65] + Ks[256][65]  = 201792 bytes.
__global__ void __launch_bounds__(256) score_softmax(const float* __restrict__ Q,
                                                     const float* __restrict__ K,
                                                     float* __restrict__ P) {
    extern __shared__ float sm[];
    float* sc = sm;                      // 16*2048
    float* Qs = sm + 16 * 2048;          // 16*65
    float* Ks = Qs + 16 * 65;            // 256*65
    int tid = threadIdx.x;
    int i0g = blockIdx.x * 16;
    int h   = blockIdx.y;
    int b   = blockIdx.z;

    const float* Qbase = Q + (size_t)(b * NS + i0g) * ND + h * NDH;
    const float* Kbase = K + (size_t)(b * NS) * ND + h * NDH;

    // load Q tile: 16 x 64
    {
        int r = tid >> 4, c4 = (tid & 15) * 4;
        float4 v = *(const float4*)(Qbase + (size_t)r * ND + c4);
        float* q = &Qs[r * 65 + c4];
        q[0] = v.x; q[1] = v.y; q[2] = v.z; q[3] = v.w;
    }

    int posI = tid >> 6;         // 0..3  -> i0 = posI*4
    int i0   = posI * 4;
    int posJ = tid & 63;         // j in {posJ, posJ+64, posJ+128, posJ+192}

    for (int jt = 0; jt < NS; jt += 256) {
        // load K tile 256 x 64
#pragma unroll
        for (int l = 0; l < 16; l++) {
            int f = tid + l * 256;
            int r = f >> 4, c4 = (f & 15) * 4;
            float4 v = *(const float4*)(Kbase + (size_t)(jt + r) * ND + c4);
            float* kk = &Ks[r * 65 + c4];
            kk[0] = v.x; kk[1] = v.y; kk[2] = v.z; kk[3] = v.w;
        }
        __syncthreads();

        float accS[4][4] = {};
#pragma unroll 16
        for (int d = 0; d < 64; d++) {
            float q0 = Qs[(i0)     * 65 + d];
            float q1 = Qs[(i0 + 1) * 65 + d];
            float q2 = Qs[(i0 + 2) * 65 + d];
            float q3 = Qs[(i0 + 3) * 65 + d];
            float k0v = Ks[(posJ)       * 65 + d];
            float k1v = Ks[(posJ +  64) * 65 + d];
            float k2v = Ks[(posJ + 128) * 65 + d];
            float k3v = Ks[(posJ + 192) * 65 + d];
            accS[0][0] += q0 * k0v; accS[0][1] += q0 * k1v; accS[0][2] += q0 * k2v; accS[0][3] += q0 * k3v;
            accS[1][0] += q1 * k0v; accS[1][1] += q1 * k1v; accS[1][2] += q1 * k2v; accS[1][3] += q1 * k3v;
            accS[2][0] += q2 * k0v; accS[2][1] += q2 * k1v; accS[2][2] += q2 * k2v; accS[2][3] += q2 * k3v;
            accS[3][0] += q3 * k0v; accS[3][1] += q3 * k1v; accS[3][2] += q3 * k2v; accS[3][3] += q3 * k3v;
        }
#pragma unroll
        for (int ii = 0; ii < 4; ii++)
#pragma unroll
            for (int jj = 0; jj < 4; jj++)
                sc[(i0 + ii) * 2048 + jt + posJ + jj * 64] = accS[ii][jj] * SCORE_SCALE;
        __syncthreads();   // protect Ks reuse
    }

    // softmax over each of the 16 rows; each warp handles 2 rows
    int w = tid >> 5, lane = tid & 31;
    for (int r = w; r < 16; r += 8) {
        float* row = sc + r * 2048;
        float m = -1e30f;
        for (int j = lane; j < 2048; j += 32) m = fmaxf(m, row[j]);
#pragma unroll
        for (int o = 16; o; o >>= 1) m = fmaxf(m, __shfl_xor_sync(0xffffffffu, m, o));
        float s = 0.f;
        for (int j = lane; j < 2048; j += 32) {
            float e = __expf(row[j] - m);
            row[j] = e;
            s += e;
        }
#pragma unroll
        for (int o = 16; o; o >>= 1) s += __shfl_xor_sync(0xffffffffu, s, o);
        float inv = 1.0f / s;
        size_t base = ((size_t)(b * NH + h) * NS + (i0g + r)) * NS;
        for (int j = lane; j < 2048; j += 32) P[base + j] = row[j] * inv;
    }
}

// ---------------- blend + interleave into final [b][i][j][h] layout ----------------
__global__ void __launch_bounds__(256) blend_kernel(float* __restrict__ outP) {
    __shared__ float sb[12 * 515];
    int i = blockIdx.x, b = blockIdx.y;
    int tid = threadIdx.x;
    size_t outBase = ((size_t)(b * NS + i)) * ((size_t)NS * NH);
    for (int jt = 0; jt < NS; jt += 512) {
#pragma unroll
        for (int l = 0; l < 24; l++) {
            int e = tid + l * 256;            // 0..6143
            int h = e >> 9, j = e & 511;
            size_t idxI = ((size_t)(b * NH + h) * NS + i) * NS + jt + j;
            size_t idxP = ((size_t)h * NS + i) * NS + jt + j;
            sb[h * 515 + j] = 0.5f * (g_Pinp[idxI] + g_Ppos[idxP]);
        }
        __syncthreads();
#pragma unroll
        for (int l = 0; l < 24; l++) {
            int e = tid + l * 256;
            int j = e / 12, h = e - j * 12;
            outP[outBase + (size_t)jt * NH + e] = sb[h * 515 + j];
        }
        __syncthreads();
    }
}

// ---------------- PV: AO[b*s][h*64+d] = sum_j 0.5*(Pinp+Ppos)[b,h,i,j] * V[b*j][h*64+d] ----------
__global__ void __launch_bounds__(256) pv_kernel() {
    __shared__ float As[64][33];   // [i][k]
    __shared__ float Vs[32][68];   // [k][d]
    int tid = threadIdx.x;
    int i0g = blockIdx.x * 64, h = blockIdx.y, b = blockIdx.z;
    int posI = tid >> 4, posD = tid & 15;
    int i0 = posI * 4, d0 = posD * 4;
    float acc[4][4] = {};
    const float* Pi = g_Pinp + ((size_t)(b * NH + h) * NS + i0g) * NS;
    const float* Pp = g_Ppos + ((size_t)h * NS + i0g) * NS;
    const float* Vb = g_V + (size_t)(b * NS) * ND + h * NDH;

    for (int k0 = 0; k0 < NS; k0 += 32) {
#pragma unroll
        for (int l = 0; l < 2; l++) {
            int f = tid + l * 256;
            int r = f >> 3, j4 = (f & 7) * 4;
            size_t off = (size_t)r * NS + k0 + j4;
            float4 a = *(const float4*)(Pi + off);
            float4 p = *(const float4*)(Pp + off);
            float* dst = &As[r][j4];
            dst[0] = 0.5f * (a.x + p.x); dst[1] = 0.5f * (a.y + p.y);
            dst[2] = 0.5f * (a.z + p.z); dst[3] = 0.5f * (a.w + p.w);
        }
#pragma unroll
        for (int l = 0; l < 2; l++) {
            int f = tid + l * 256;
            int r = f >> 4, c4 = (f & 15) * 4;
            float4 v = *(const float4*)(Vb + (size_t)(k0 + r) * ND + c4);
            *(float4*)&Vs[r][c4] = v;
        }
        __syncthreads();
#pragma unroll
        for (int k = 0; k < 32; k++) {
            float a0 = As[i0][k], a1 = As[i0 + 1][k], a2 = As[i0 + 2][k], a3 = As[i0 + 3][k];
            float4 v4 = *(const float4*)&Vs[k][d0];
            acc[0][0] += a0 * v4.x; acc[0][1] += a0 * v4.y; acc[0][2] += a0 * v4.z; acc[0][3] += a0 * v4.w;
            acc[1][0] += a1 * v4.x; acc[1][1] += a1 * v4.y; acc[1][2] += a1 * v4.z; acc[1][3] += a1 * v4.w;
            acc[2][0] += a2 * v4.x; acc[2][1] += a2 * v4.y; acc[2][2] += a2 * v4.z; acc[2][3] += a2 * v4.w;
            acc[3][0] += a3 * v4.x; acc[3][1] += a3 * v4.y; acc[3][2] += a3 * v4.z; acc[3][3] += a3 * v4.w;
        }
        __syncthreads();
    }
#pragma unroll
    for (int ii = 0; ii < 4; ii++) {
        float4 o = make_float4(acc[ii][0], acc[ii][1], acc[ii][2], acc[ii][3]);
        *(float4*)(g_AO + (size_t)(b * NS + i0g + i0 + ii) * ND + h * NDH + d0) = o;
    }
}

// ---------------- launch ----------------
extern "C" void kernel_launch(void* const* d_in, const int* in_sizes, int n_in,
                              void* d_out, int out_size) {
    (void)in_sizes; (void)n_in; (void)out_size;
    const float* inp    = (const float*)d_in[0];
    const float* pos    = (const float*)d_in[1];
    const float* Wq_inp = (const float*)d_in[2];
    const float* Wk_inp = (const float*)d_in[3];
    const float* Wq_pos = (const float*)d_in[4];
    const float* Wk_pos = (const float*)d_in[5];
    const float* Wv     = (const float*)d_in[6];
    const float* Wo     = (const float*)d_in[7];

    float* out      = (float*)d_out;
    float* out_attn = out;                                   // [B,S,D]
    float* out_prob = out + (size_t)NBAT * NS * ND;          // [B,S,S,H]

    // symbol addresses for scratch
    float *pW5, *pQ, *pK, *pV, *pQp, *pKp, *pPinp, *pPpos, *pAO;
    cudaGetSymbolAddress((void**)&pW5,   g_W5);
    cudaGetSymbolAddress((void**)&pQ,    g_Q);
    cudaGetSymbolAddress((void**)&pK,    g_K);
    cudaGetSymbolAddress((void**)&pV,    g_V);
    cudaGetSymbolAddress((void**)&pQp,   g_Qp);
    cudaGetSymbolAddress((void**)&pKp,   g_Kp);
    cudaGetSymbolAddress((void**)&pPinp, g_Pinp);
    cudaGetSymbolAddress((void**)&pPpos, g_Ppos);
    cudaGetSymbolAddress((void**)&pAO,   g_AO);

    const int WELEM = 768 * 768;
    int permGrid = (WELEM + 255) / 256;
    permW<<<permGrid, 256>>>(Wq_inp, pW5 + 0 * WELEM);
    permW<<<permGrid, 256>>>(Wk_inp, pW5 + 1 * WELEM);
    permW<<<permGrid, 256>>>(Wq_pos, pW5 + 2 * WELEM);
    permW<<<permGrid, 256>>>(Wk_pos, pW5 + 3 * WELEM);
    permW<<<permGrid, 256>>>(Wv,     pW5 + 4 * WELEM);

    // projections
    {
        dim3 gI(4096 / 64, 768 / 64);
        sgemm64<<<gI, 256>>>(inp, pW5 + 0 * WELEM, pQ, 4096, 768, 768);
        sgemm64<<<gI, 256>>>(inp, pW5 + 1 * WELEM, pK, 4096, 768, 768);
        sgemm64<<<gI, 256>>>(inp, pW5 + 4 * WELEM, pV, 4096, 768, 768);
        dim3 gP(2048 / 64, 768 / 64);
        sgemm64<<<gP, 256>>>(pos, pW5 + 2 * WELEM, pQp, 2048, 768, 768);
        sgemm64<<<gP, 256>>>(pos, pW5 + 3 * WELEM, pKp, 2048, 768, 768);
    }

    // scores + softmax
    {
        int dynBytes = (16 * 2048 + 16 * 65 + 256 * 65) * (int)sizeof(float);   // 201792
        cudaFuncSetAttribute(score_softmax, cudaFuncAttributeMaxDynamicSharedMemorySize, dynBytes);
        dim3 gInp(NS / 16, NH, NBAT);
        score_softmax<<<gInp, 256, dynBytes>>>(pQ, pK, pPinp);
        dim3 gPos(NS / 16, NH, 1);
        score_softmax<<<gPos, 256, dynBytes>>>(pQp, pKp, pPpos);
    }

    // blend + interleave -> out_prob
    {
        dim3 g(NS, NBAT);
        blend_kernel<<<g, 256>>>(out_prob);
    }

    // PV
    {
        dim3 g(NS / 64, NH, NBAT);
        pv_kernel<<<g, 256>>>();
    }

    // final output projection
    {
        dim3 g(4096 / 64, 768 / 64);
        sgemm64<<<g, 256>>>(pAO, Wo, out_attn, 4096, 768, 768);
    }
}

// round 6
// speedup vs baseline: 2.3950x; 2.3950x over previous
#include <cuda_runtime.h>
#include <math.h>

#define NS   2048
#define NBAT 2
#define ND   768
#define NH   12
#define NDH  64
static const float SCORE_SCALE = 0.125f;   // 1/sqrt(64) * smoothing

// ---------------- scratch ----------------
__device__ float g_W5[5][768 * 768];                       // permuted weights [k][h*64+d]
__device__ float g_Q [4096 * 768];
__device__ float g_K [4096 * 768];
__device__ float g_V [4096 * 768];
__device__ float g_Qp[2048 * 768];
__device__ float g_Kp[2048 * 768];
__device__ float g_Einp[(size_t)2 * 12 * 2048 * 2048];     // exp(scores), unnormalized
__device__ float g_Epos[(size_t)12 * 2048 * 2048];
__device__ float g_sumI[2 * 12 * 2048];                    // row sums
__device__ float g_sumP[12 * 2048];
__device__ float g_AO[4096 * 768];

// ---------------- helpers ----------------
__device__ __forceinline__ unsigned f2tf(float x) {
    unsigned r; asm("cvt.rna.tf32.f32 %0, %1;" : "=r"(r) : "f"(x)); return r;
}
__device__ __forceinline__ float f2tff(float x) { return __uint_as_float(f2tf(x)); }
__device__ __forceinline__ void mma8(float c[4], const unsigned a[4], const unsigned b[2]) {
    asm volatile(
        "mma.sync.aligned.m16n8k8.row.col.f32.tf32.tf32.f32 "
        "{%0,%1,%2,%3},{%4,%5,%6,%7},{%8,%9},{%0,%1,%2,%3};"
        : "+f"(c[0]), "+f"(c[1]), "+f"(c[2]), "+f"(c[3])
        : "r"(a[0]), "r"(a[1]), "r"(a[2]), "r"(a[3]), "r"(b[0]), "r"(b[1]));
}

// ---------------- weight permutation ----------------
__global__ void permW(const float* __restrict__ W, float* __restrict__ Wp) {
    int idx = blockIdx.x * 256 + threadIdx.x;
    if (idx >= 768 * 768) return;
    int k = idx / 768;
    int oc = idx - k * 768;
    int h = oc >> 6, d = oc & 63;
    Wp[idx] = W[k * 768 + d * 12 + h];
}

// ---------------- tf32 MMA GEMM: C[M,N]=A[M,K]@B[K,N], BM=64 BN=128 BK=32 ----------------
__global__ void __launch_bounds__(256) gemm_tf32(const float* __restrict__ A,
                                                 const float* __restrict__ B,
                                                 float* __restrict__ C,
                                                 int M, int N, int K) {
    __shared__ float As[64 * 36];
    __shared__ float Bs[32 * 132];
    int tid = threadIdx.x;
    int lane = tid & 31, wid = tid >> 5;
    int g = lane >> 2, t = lane & 3;
    int warpM = wid >> 2, warpN = wid & 3;        // 2 x 4 warps, 32x32 tiles
    int row0 = blockIdx.x * 64, col0 = blockIdx.y * 128;

    float c[2][4][4] = {};
    int ar = tid >> 3, ac = (tid & 7) * 4;        // A loader: rows ar, ar+32
    int br = tid >> 5, bc = (tid & 31) * 4;       // B loader: rows br+8*rr

    for (int k0 = 0; k0 < K; k0 += 32) {
        float4 a0 = *(const float4*)(A + (size_t)(row0 + ar) * K + k0 + ac);
        float4 a1 = *(const float4*)(A + (size_t)(row0 + ar + 32) * K + k0 + ac);
        float* d0 = &As[ar * 36 + ac];
        d0[0] = f2tff(a0.x); d0[1] = f2tff(a0.y); d0[2] = f2tff(a0.z); d0[3] = f2tff(a0.w);
        float* d1 = &As[(ar + 32) * 36 + ac];
        d1[0] = f2tff(a1.x); d1[1] = f2tff(a1.y); d1[2] = f2tff(a1.z); d1[3] = f2tff(a1.w);
#pragma unroll
        for (int rr = 0; rr < 4; rr++) {
            int r = br + rr * 8;
            float4 bv = *(const float4*)(B + (size_t)(k0 + r) * N + col0 + bc);
            float* db = &Bs[r * 132 + bc];
            db[0] = f2tff(bv.x); db[1] = f2tff(bv.y); db[2] = f2tff(bv.z); db[3] = f2tff(bv.w);
        }
        __syncthreads();
        const unsigned* Au = (const unsigned*)As;
        const unsigned* Bu = (const unsigned*)Bs;
#pragma unroll
        for (int kk = 0; kk < 4; kk++) {
            int k8 = kk * 8;
            unsigned a[2][4], b[4][2];
#pragma unroll
            for (int mi = 0; mi < 2; mi++) {
                int m = warpM * 32 + mi * 16;
                a[mi][0] = Au[(m + g) * 36 + k8 + t];
                a[mi][1] = Au[(m + g + 8) * 36 + k8 + t];
                a[mi][2] = Au[(m + g) * 36 + k8 + t + 4];
                a[mi][3] = Au[(m + g + 8) * 36 + k8 + t + 4];
            }
#pragma unroll
            for (int ni = 0; ni < 4; ni++) {
                int n = warpN * 32 + ni * 8;
                b[ni][0] = Bu[(k8 + t) * 132 + n + g];
                b[ni][1] = Bu[(k8 + t + 4) * 132 + n + g];
            }
#pragma unroll
            for (int mi = 0; mi < 2; mi++)
#pragma unroll
                for (int ni = 0; ni < 4; ni++)
                    mma8(c[mi][ni], a[mi], b[ni]);
        }
        __syncthreads();
    }
#pragma unroll
    for (int mi = 0; mi < 2; mi++) {
#pragma unroll
        for (int ni = 0; ni < 4; ni++) {
            int row = row0 + warpM * 32 + mi * 16 + g;
            int col = col0 + warpN * 32 + ni * 8 + 2 * t;
            *(float2*)(C + (size_t)row * N + col) = make_float2(c[mi][ni][0], c[mi][ni][1]);
            *(float2*)(C + (size_t)(row + 8) * N + col) = make_float2(c[mi][ni][2], c[mi][ni][3]);
        }
    }
}

// ---------------- scores: E = exp(scale * Q K^T), plus row sums ----------------
// grid: (NS/128, NH, nb). dyn smem: Qs[128*68] + Ks[64*68] + rbuf[256]
__global__ void __launch_bounds__(256) score_exp(const float* __restrict__ Q,
                                                 const float* __restrict__ Km,
                                                 float* __restrict__ E,
                                                 float* __restrict__ sums) {
    extern __shared__ float sm[];
    float* Qs = sm;                 // 128*68
    float* Ks = sm + 128 * 68;      // 64*68
    float* rbuf = Ks + 64 * 68;     // 256
    int tid = threadIdx.x;
    int lane = tid & 31, wid = tid >> 5;
    int g = lane >> 2, t = lane & 3;
    int warpM = wid >> 1, warpN = wid & 1;      // 4 x 2, warp tile 32x32
    int i0 = blockIdx.x * 128;
    int h = blockIdx.y, b = blockIdx.z;
    int plane = b * NH + h;

    const float* qb = Q + ((size_t)b * NS + i0) * ND + h * NDH;
    const float* kb = Km + (size_t)b * NS * ND + h * NDH;
    float* Ep = E + (size_t)plane * NS * NS;

    // load Q tile 128x64
#pragma unroll
    for (int l = 0; l < 8; l++) {
        int idx = tid + l * 256;
        int r = idx >> 4, c = (idx & 15) * 4;
        float4 v = *(const float4*)(qb + (size_t)r * ND + c);
        float* d = &Qs[r * 68 + c];
        d[0] = f2tff(v.x); d[1] = f2tff(v.y); d[2] = f2tff(v.z); d[3] = f2tff(v.w);
    }

    float rs[2][2] = {};   // row-sum partials: [mi][half]

    for (int jt = 0; jt < NS; jt += 64) {
#pragma unroll
        for (int l = 0; l < 4; l++) {
            int idx = tid + l * 256;
            int r = idx >> 4, c = (idx & 15) * 4;
            float4 v = *(const float4*)(kb + (size_t)(jt + r) * ND + c);
            float* d = &Ks[r * 68 + c];
            d[0] = f2tff(v.x); d[1] = f2tff(v.y); d[2] = f2tff(v.z); d[3] = f2tff(v.w);
        }
        __syncthreads();

        float c4[2][4][4] = {};
        const unsigned* Qu = (const unsigned*)Qs;
        const unsigned* Ku = (const unsigned*)Ks;
#pragma unroll
        for (int kk = 0; kk < 8; kk++) {
            int k8 = kk * 8;
            unsigned a[2][4], bfr[4][2];
#pragma unroll
            for (int mi = 0; mi < 2; mi++) {
                int m = warpM * 32 + mi * 16;
                a[mi][0] = Qu[(m + g) * 68 + k8 + t];
                a[mi][1] = Qu[(m + g + 8) * 68 + k8 + t];
                a[mi][2] = Qu[(m + g) * 68 + k8 + t + 4];
                a[mi][3] = Qu[(m + g + 8) * 68 + k8 + t + 4];
            }
#pragma unroll
            for (int ni = 0; ni < 4; ni++) {
                int n = warpN * 32 + ni * 8;
                bfr[ni][0] = Ku[(n + g) * 68 + k8 + t];
                bfr[ni][1] = Ku[(n + g) * 68 + k8 + t + 4];
            }
#pragma unroll
            for (int mi = 0; mi < 2; mi++)
#pragma unroll
                for (int ni = 0; ni < 4; ni++)
                    mma8(c4[mi][ni], a[mi], bfr[ni]);
        }
        // exp + row-sum + store
#pragma unroll
        for (int mi = 0; mi < 2; mi++) {
#pragma unroll
            for (int ni = 0; ni < 4; ni++) {
                float e0 = __expf(c4[mi][ni][0] * SCORE_SCALE);
                float e1 = __expf(c4[mi][ni][1] * SCORE_SCALE);
                float e2 = __expf(c4[mi][ni][2] * SCORE_SCALE);
                float e3 = __expf(c4[mi][ni][3] * SCORE_SCALE);
                rs[mi][0] += e0 + e1;
                rs[mi][1] += e2 + e3;
                int row = i0 + warpM * 32 + mi * 16 + g;
                int col = jt + warpN * 32 + ni * 8 + 2 * t;
                *(float2*)(Ep + (size_t)row * NS + col) = make_float2(e0, e1);
                *(float2*)(Ep + (size_t)(row + 8) * NS + col) = make_float2(e2, e3);
            }
        }
        __syncthreads();
    }

    // reduce row sums over t (lanes in a group), then across the 2 N-warps
#pragma unroll
    for (int mi = 0; mi < 2; mi++)
#pragma unroll
        for (int hf = 0; hf < 2; hf++) {
            float v = rs[mi][hf];
            v += __shfl_xor_sync(0xffffffffu, v, 1);
            v += __shfl_xor_sync(0xffffffffu, v, 2);
            rs[mi][hf] = v;
        }
    if (t == 0) {
#pragma unroll
        for (int mi = 0; mi < 2; mi++)
#pragma unroll
            for (int hf = 0; hf < 2; hf++) {
                int r = warpM * 32 + mi * 16 + hf * 8 + g;
                rbuf[r * 2 + warpN] = rs[mi][hf];
            }
    }
    __syncthreads();
    if (tid < 128)
        sums[(size_t)plane * NS + i0 + tid] = rbuf[tid * 2] + rbuf[tid * 2 + 1];
}

// ---------------- blend + interleave into [b][i][j][h] ----------------
__global__ void __launch_bounds__(256) blend_kernel(float* __restrict__ outP) {
    __shared__ float sb[12 * 515];
    __shared__ float sIs[12], sPs[12];
    int b = blockIdx.x, i = blockIdx.y;
    int tid = threadIdx.x;
    if (tid < 12) sIs[tid] = 0.5f / g_sumI[(b * 12 + tid) * NS + i];
    else if (tid < 24) sPs[tid - 12] = 0.5f / g_sumP[(tid - 12) * NS + i];
    __syncthreads();
    size_t outBase = ((size_t)(b * NS + i)) * ((size_t)NS * NH);
    for (int jt = 0; jt < NS; jt += 512) {
#pragma unroll
        for (int l = 0; l < 24; l++) {
            int e = tid + l * 256;
            int h = e >> 9, j = e & 511;
            size_t idxI = ((size_t)(b * NH + h) * NS + i) * NS + jt + j;
            size_t idxP = ((size_t)h * NS + i) * NS + jt + j;
            sb[h * 515 + j] = g_Einp[idxI] * sIs[h] + g_Epos[idxP] * sPs[h];
        }
        __syncthreads();
#pragma unroll
        for (int l = 0; l < 24; l++) {
            int e = tid + l * 256;
            int j = e / 12, h = e - j * 12;
            outP[outBase + (size_t)jt * NH + e] = sb[h * 515 + j];
        }
        __syncthreads();
    }
}

// ---------------- PV (tf32 MMA): AO = blend(P) @ V ----------------
// grid: (NS/64, NBAT, NH). CTA tile 64(i) x 64(d), K loop over j in 32-chunks.
__global__ void __launch_bounds__(256) pv_mma() {
    __shared__ float As[64 * 36];
    __shared__ float Vs[32 * 68];
    __shared__ float invI[64], invP[64];
    int tid = threadIdx.x;
    int lane = tid & 31, wid = tid >> 5;
    int g = lane >> 2, t = lane & 3;
    int warpM = wid >> 1, warpN = wid & 1;       // 4 x 2, warp tile 16x32
    int i0 = blockIdx.x * 64;
    int b = blockIdx.y, h = blockIdx.z;
    int plane = b * NH + h;

    const float* Ei = g_Einp + (size_t)plane * NS * NS;
    const float* Epp = g_Epos + (size_t)h * NS * NS;
    const float* Vb = g_V + (size_t)b * NS * ND + h * NDH;

    if (tid < 64) invI[tid] = 0.5f / g_sumI[(size_t)plane * NS + i0 + tid];
    else if (tid < 128) invP[tid - 64] = 0.5f / g_sumP[(size_t)h * NS + i0 + tid - 64];
    __syncthreads();

    float c4[4][4] = {};
    int ar = tid >> 3, ac = (tid & 7) * 4;   // A loader rows ar, ar+32 (i), cols j

    for (int k0 = 0; k0 < NS; k0 += 32) {
#pragma unroll
        for (int rr = 0; rr < 2; rr++) {
            int r = ar + rr * 32;
            size_t off = (size_t)(i0 + r) * NS + k0 + ac;
            float4 e1 = *(const float4*)(Ei + off);
            float4 e2 = *(const float4*)(Epp + off);
            float si = invI[r], sp = invP[r];
            float* d = &As[r * 36 + ac];
            d[0] = f2tff(e1.x * si + e2.x * sp);
            d[1] = f2tff(e1.y * si + e2.y * sp);
            d[2] = f2tff(e1.z * si + e2.z * sp);
            d[3] = f2tff(e1.w * si + e2.w * sp);
        }
        // V loader: full 32(j) x 64(d) tile = 512 float4s over 256 threads (2 each)
#pragma unroll
        for (int l = 0; l < 2; l++) {
            int f = tid + l * 256;
            int r = f >> 4, c = (f & 15) * 4;
            float4 vv = *(const float4*)(Vb + (size_t)(k0 + r) * ND + c);
            float* dv = &Vs[r * 68 + c];
            dv[0] = f2tff(vv.x); dv[1] = f2tff(vv.y); dv[2] = f2tff(vv.z); dv[3] = f2tff(vv.w);
        }
        __syncthreads();

        const unsigned* Au = (const unsigned*)As;
        const unsigned* Vu = (const unsigned*)Vs;
#pragma unroll
        for (int kk = 0; kk < 4; kk++) {
            int k8 = kk * 8;
            unsigned a[4], bfr[4][2];
            int m = warpM * 16;
            a[0] = Au[(m + g) * 36 + k8 + t];
            a[1] = Au[(m + g + 8) * 36 + k8 + t];
            a[2] = Au[(m + g) * 36 + k8 + t + 4];
            a[3] = Au[(m + g + 8) * 36 + k8 + t + 4];
#pragma unroll
            for (int ni = 0; ni < 4; ni++) {
                int n = warpN * 32 + ni * 8;
                bfr[ni][0] = Vu[(k8 + t) * 68 + n + g];
                bfr[ni][1] = Vu[(k8 + t + 4) * 68 + n + g];
            }
#pragma unroll
            for (int ni = 0; ni < 4; ni++)
                mma8(c4[ni], a, bfr[ni]);
        }
        __syncthreads();
    }
#pragma unroll
    for (int ni = 0; ni < 4; ni++) {
        int row = i0 + warpM * 16 + g;
        int col = warpN * 32 + ni * 8 + 2 * t;
        float* dst = g_AO + (size_t)(b * NS + row) * ND + h * NDH + col;
        *(float2*)dst = make_float2(c4[ni][0], c4[ni][1]);
        *(float2*)(dst + (size_t)8 * ND) = make_float2(c4[ni][2], c4[ni][3]);
    }
}

// ---------------- launch ----------------
extern "C" void kernel_launch(void* const* d_in, const int* in_sizes, int n_in,
                              void* d_out, int out_size) {
    (void)in_sizes; (void)n_in; (void)out_size;
    const float* inp    = (const float*)d_in[0];
    const float* pos    = (const float*)d_in[1];
    const float* Wq_inp = (const float*)d_in[2];
    const float* Wk_inp = (const float*)d_in[3];
    const float* Wq_pos = (const float*)d_in[4];
    const float* Wk_pos = (const float*)d_in[5];
    const float* Wv     = (const float*)d_in[6];
    const float* Wo     = (const float*)d_in[7];

    float* out      = (float*)d_out;
    float* out_attn = out;
    float* out_prob = out + (size_t)NBAT * NS * ND;

    float *pW5, *pQ, *pK, *pV, *pQp, *pKp, *pEi, *pEp, *pSi, *pSp, *pAO;
    cudaGetSymbolAddress((void**)&pW5, g_W5);
    cudaGetSymbolAddress((void**)&pQ,  g_Q);
    cudaGetSymbolAddress((void**)&pK,  g_K);
    cudaGetSymbolAddress((void**)&pV,  g_V);
    cudaGetSymbolAddress((void**)&pQp, g_Qp);
    cudaGetSymbolAddress((void**)&pKp, g_Kp);
    cudaGetSymbolAddress((void**)&pEi, g_Einp);
    cudaGetSymbolAddress((void**)&pEp, g_Epos);
    cudaGetSymbolAddress((void**)&pSi, g_sumI);
    cudaGetSymbolAddress((void**)&pSp, g_sumP);
    cudaGetSymbolAddress((void**)&pAO, g_AO);

    const int WELEM = 768 * 768;
    int permGrid = (WELEM + 255) / 256;
    permW<<<permGrid, 256>>>(Wq_inp, pW5 + 0 * WELEM);
    permW<<<permGrid, 256>>>(Wk_inp, pW5 + 1 * WELEM);
    permW<<<permGrid, 256>>>(Wq_pos, pW5 + 2 * WELEM);
    permW<<<permGrid, 256>>>(Wk_pos, pW5 + 3 * WELEM);
    permW<<<permGrid, 256>>>(Wv,     pW5 + 4 * WELEM);

    {
        dim3 gI(4096 / 64, 768 / 128);
        gemm_tf32<<<gI, 256>>>(inp, pW5 + 0 * WELEM, pQ, 4096, 768, 768);
        gemm_tf32<<<gI, 256>>>(inp, pW5 + 1 * WELEM, pK, 4096, 768, 768);
        gemm_tf32<<<gI, 256>>>(inp, pW5 + 4 * WELEM, pV, 4096, 768, 768);
        dim3 gP(2048 / 64, 768 / 128);
        gemm_tf32<<<gP, 256>>>(pos, pW5 + 2 * WELEM, pQp, 2048, 768, 768);
        gemm_tf32<<<gP, 256>>>(pos, pW5 + 3 * WELEM, pKp, 2048, 768, 768);
    }

    {
        int dynBytes = (128 * 68 + 64 * 68 + 256) * (int)sizeof(float);   // 53248
        cudaFuncSetAttribute(score_exp, cudaFuncAttributeMaxDynamicSharedMemorySize, dynBytes);
        dim3 gInp(NS / 128, NH, NBAT);
        score_exp<<<gInp, 256, dynBytes>>>(pQ, pK, pEi, pSi);
        dim3 gPos(NS / 128, NH, 1);
        score_exp<<<gPos, 256, dynBytes>>>(pQp, pKp, pEp, pSp);
    }

    {
        dim3 g(NBAT, NS);
        blend_kernel<<<g, 256>>>(out_prob);
    }

    {
        dim3 g(NS / 64, NBAT, NH);
        pv_mma<<<g, 256>>>();
    }

    {
        dim3 g(4096 / 64, 768 / 128);
        gemm_tf32<<<g, 256>>>(pAO, Wo, out_attn, 4096, 768, 768);
    }
}